// round 15
// baseline (speedup 1.0000x reference)
#include <cuda_runtime.h>
#include <cuda_bf16.h>
#include <cstdint>

#define BATCH 64
#define TCAP  32
#define VOCAB 32000
#define EDIM  1024
#define DDIM  1024
#define TDEC  31
#define NG    4096
#define MROWS 2048
#define CROW  144
#define NCHUNK 16
#define KSPLIT 4
#define NTILES 32          // 4096 / 128

// ---------------- static scratch ----------------
__device__ int   d_sortind[BATCH];
__device__ int   d_declen[BATCH];
__device__ int   d_cnt[TDEC];
__device__ int   d_rowstart[TDEC];
__device__ int   d_Mact;
__device__ int   d_M2048 = 2048;
__device__ int   d_i64;
__device__ int   d_ncnt[NTILES];
__device__ long long d_rowout[MROWS];
__device__ __align__(16) float d_gatesx[TCAP * BATCH * NG];   // gate-PACKED cols
__device__ __align__(16) float d_biasPk[NG];
__device__ __align__(16) float d_c[BATCH * DDIM];
__device__ __align__(16) float d_part[KSPLIT][BATCH][NG];
// chunked + padded bf16 operands: [chunk][row][144B]
__device__ __align__(16) char d_XhiC [NCHUNK * MROWS * CROW];
__device__ __align__(16) char d_XloC [NCHUNK * MROWS * CROW];
__device__ __align__(16) char d_HchiC[NCHUNK * MROWS * CROW];
__device__ __align__(16) char d_HcloC[NCHUNK * MROWS * CROW];
__device__ __align__(16) char d_WihHiC[NCHUNK * NG * CROW];   // gate-packed rows
__device__ __align__(16) char d_WihLoC[NCHUNK * NG * CROW];
__device__ __align__(16) char d_WhhHiC[NCHUNK * NG * CROW];
__device__ __align__(16) char d_WhhLoC[NCHUNK * NG * CROW];
__device__ __align__(16) char d_WfcHiC[NCHUNK * VOCAB * CROW];
__device__ __align__(16) char d_WfcLoC[NCHUNK * VOCAB * CROW];
__device__ __align__(16) char d_HpHi[2][NCHUNK * BATCH * CROW];
__device__ __align__(16) char d_HpLo[2][NCHUNK * BATCH * CROW];

__device__ __forceinline__ float sigmf(float x) { return 1.0f / (1.0f + expf(-x)); }

__device__ __forceinline__ uint32_t smem_u32(const void* p) {
    uint32_t a;
    asm("{ .reg .u64 t; cvta.to.shared.u64 t, %1; cvt.u32.u64 %0, t; }" : "=r"(a) : "l"(p));
    return a;
}

#define LDSM4(r0, r1, r2, r3, a) \
    asm volatile("ldmatrix.sync.aligned.m8n8.x4.shared.b16 {%0,%1,%2,%3}, [%4];" \
                 : "=r"(r0), "=r"(r1), "=r"(r2), "=r"(r3) : "r"(a))
#define LDSM2(r0, r1, a) \
    asm volatile("ldmatrix.sync.aligned.m8n8.x2.shared.b16 {%0,%1}, [%2];" \
                 : "=r"(r0), "=r"(r1) : "r"(a))
#define MMA16816(c, a, b) \
    asm volatile("mma.sync.aligned.m16n8k16.row.col.f32.bf16.bf16.f32 " \
                 "{%0,%1,%2,%3}, {%4,%5,%6,%7}, {%8,%9}, {%0,%1,%2,%3};" \
                 : "+f"((c)[0]), "+f"((c)[1]), "+f"((c)[2]), "+f"((c)[3]) \
                 : "r"((a)[0]), "r"((a)[1]), "r"((a)[2]), "r"((a)[3]), "r"((b)[0]), "r"((b)[1]))
#define MBAR_INIT(a, c)  asm volatile("mbarrier.init.shared.b64 [%0], %1;" :: "r"(a), "r"(c) : "memory")
#define MBAR_EXPECT(a, tx) asm volatile("mbarrier.arrive.expect_tx.shared.b64 _, [%0], %1;" :: "r"(a), "r"(tx) : "memory")
#define FENCE_ASYNC()    asm volatile("fence.proxy.async.shared::cta;" ::: "memory")
#define BULKCP(dst, src, sz, mb) \
    asm volatile("cp.async.bulk.shared::cluster.global.mbarrier::complete_tx::bytes [%0], [%1], %2, [%3];" \
                 :: "r"(dst), "l"(src), "r"(sz), "r"(mb) : "memory")

__device__ __forceinline__ void mbar_wait(uint32_t mb, uint32_t parity) {
    asm volatile(
        "{\n\t.reg .pred P;\n\t"
        "W%=:\n\t"
        "mbarrier.try_wait.parity.acquire.cta.shared::cta.b64 P, [%0], %1, 0x989680;\n\t"
        "@P bra.uni D%=;\n\t"
        "bra.uni W%=;\n\t"
        "D%=:\n\t}" :: "r"(mb), "r"(parity) : "memory");
}

// ---------------- setup ----------------
__global__ void k_setup(const void* __restrict__ cap_len_raw)
{
    __shared__ int len[BATCH];
    const int* p32 = (const int*)cap_len_raw;
    int is64 = (p32[1] == 0) ? 1 : 0;   // lengths in [2,32]; int64 high word == 0
    int i = threadIdx.x;
    if (i == 0) d_i64 = is64;
    if (i < BATCH) len[i] = p32[i << is64];
    __syncthreads();
    if (i < BATCH) {
        int li = len[i], r = 0;
        for (int j = 0; j < BATCH; j++) {
            int lj = len[j];
            if (lj > li || (lj == li && j < i)) r++;
        }
        d_sortind[r] = i;
        d_declen[r]  = li - 1;
    }
    __syncthreads();
    if (i < TDEC) {
        int c = 0;
        for (int b = 0; b < BATCH; b++)
            if (d_declen[b] > i) c++;
        d_cnt[i] = c;
    }
    __syncthreads();
    if (i == 0) {
        int acc = 0;
        for (int s = 0; s < TDEC; s++) { d_rowstart[s] = acc; acc += d_cnt[s]; }
        d_Mact = acc;
    }
    __syncthreads();
    for (int s = 0; s < TDEC; s++)
        if (i < d_cnt[s])
            d_rowout[d_rowstart[s] + i] = ((long long)i * TDEC + s) * VOCAB;
}

__global__ void k_tail(float* __restrict__ out, int out_size)
{
    int i = threadIdx.x;
    long long base = (long long)BATCH * TDEC * VOCAB;
    if (out_size >= (int)(base + 2 * BATCH) && i < BATCH) {
        out[base + i]         = (float)d_declen[i];
        out[base + BATCH + i] = (float)d_sortind[i];
    }
}

__global__ void k_packbias(const float* __restrict__ bih, const float* __restrict__ bhh)
{
    int p = blockIdx.x * 256 + threadIdx.x;
    int o = (p & 3) * 1024 + (p >> 2);
    d_biasPk[p] = bih[o] + bhh[o];
}

// ---------------- gather ----------------
__global__ void __launch_bounds__(256) k_gather(const float* __restrict__ enc,
                                                const void* __restrict__ caps_raw,
                                                const float* __restrict__ emb)
{
    int row = blockIdx.x;
    int t = row >> 6, b = row & 63;
    int sb = d_sortind[b];
    const float* src;
    if (t == 0) {
        src = enc + (long long)sb * EDIM;
    } else {
        int idx = sb * TCAP + (t - 1);
        int tok = ((const int*)caps_raw)[idx << d_i64];
        src = emb + (long long)tok * EDIM;
    }
    float4 v = ((const float4*)src)[threadIdx.x];
    __nv_bfloat16 hx = __float2bfloat16(v.x), hy = __float2bfloat16(v.y);
    __nv_bfloat16 hz = __float2bfloat16(v.z), hw = __float2bfloat16(v.w);
    __nv_bfloat162 hA; hA.x = hx; hA.y = hy;
    __nv_bfloat162 hB; hB.x = hz; hB.y = hw;
    __nv_bfloat162 lA, lB;
    lA.x = __float2bfloat16(v.x - __bfloat162float(hx));
    lA.y = __float2bfloat16(v.y - __bfloat162float(hy));
    lB.x = __float2bfloat16(v.z - __bfloat162float(hz));
    lB.y = __float2bfloat16(v.w - __bfloat162float(hw));
    int col = threadIdx.x * 4;
    int ch = col >> 6, kc = col & 63;
    size_t off = ((size_t)ch * MROWS + row) * CROW + kc * 2;
    *(__nv_bfloat162*)(d_XhiC + off)     = hA;
    *(__nv_bfloat162*)(d_XhiC + off + 4) = hB;
    *(__nv_bfloat162*)(d_XloC + off)     = lA;
    *(__nv_bfloat162*)(d_XloC + off + 4) = lB;
}

// ---------------- split weights ----------------
__global__ void __launch_bounds__(256) k_split(const float4* __restrict__ src,
                                               char* __restrict__ hiC,
                                               char* __restrict__ loC, int nrows, int perm)
{
    int r = blockIdx.x;
    int p = perm ? ((r & 1023) * 4 + (r >> 10)) : r;
    int tid = threadIdx.x;
    float4 v = src[(size_t)r * 256 + tid];
    __nv_bfloat16 hx = __float2bfloat16(v.x), hy = __float2bfloat16(v.y);
    __nv_bfloat16 hz = __float2bfloat16(v.z), hw = __float2bfloat16(v.w);
    __nv_bfloat162 hA; hA.x = hx; hA.y = hy;
    __nv_bfloat162 hB; hB.x = hz; hB.y = hw;
    __nv_bfloat162 lA, lB;
    lA.x = __float2bfloat16(v.x - __bfloat162float(hx));
    lA.y = __float2bfloat16(v.y - __bfloat162float(hy));
    lB.x = __float2bfloat16(v.z - __bfloat162float(hz));
    lB.y = __float2bfloat16(v.w - __bfloat162float(hw));
    int col = tid * 4;
    int ch = col >> 6, kc = col & 63;
    size_t off = ((size_t)ch * nrows + p) * CROW + kc * 2;
    *(__nv_bfloat162*)(hiC + off)     = hA;
    *(__nv_bfloat162*)(hiC + off + 4) = hB;
    *(__nv_bfloat162*)(loC + off)     = lA;
    *(__nv_bfloat162*)(loC + off + 4) = lB;
}

// ================= bulk-copy mma.sync GEMM (256x128, warp tile 64x64) =================
#define A_ST   (256 * CROW)          // 36864 per A operand per stage
#define B_ST   (128 * CROW)          // 18432 per B operand per stage
#define STG2   (2 * A_ST + 2 * B_ST) // 110592 per stage
#define SMEMB  (128 + 2 * STG2)      // 221312

__global__ void __launch_bounds__(256, 1) k_mma(
    const char* __restrict__ AhiC, const char* __restrict__ AloC,
    const char* __restrict__ BhiC, const char* __restrict__ BloC,
    int arows, int brows,
    const float* __restrict__ bias1,
    float* __restrict__ outp, const long long* __restrict__ rowout,
    const int* __restrict__ pMact, int mode)
{
    extern __shared__ char smem[];
    int tid = threadIdx.x;
    int m0 = blockIdx.x * 256;
    int n0 = blockIdx.y * 128;
    int Mact = *pMact;
    if (m0 >= Mact) return;

    uint32_t sb  = smem_u32(smem);
    uint32_t stg = sb + 128;
    int wid = tid >> 5, lane = tid & 31;
    int wm = wid >> 1, wn = wid & 1;      // warp tile 64x64

    if (tid == 0) { MBAR_INIT(sb + 0, 1); MBAR_INIT(sb + 8, 1); }
    FENCE_ASYNC();
    __syncthreads();

    auto issue = [&](int c, int slot) {
        uint32_t mb = sb + slot * 8;
        MBAR_EXPECT(mb, STG2);
        uint32_t base = stg + slot * STG2;
        BULKCP(base,                AhiC + ((size_t)c * arows + m0) * CROW, A_ST, mb);
        BULKCP(base + A_ST,         AloC + ((size_t)c * arows + m0) * CROW, A_ST, mb);
        BULKCP(base + 2 * A_ST,         BhiC + ((size_t)c * brows + n0) * CROW, B_ST, mb);
        BULKCP(base + 2 * A_ST + B_ST,  BloC + ((size_t)c * brows + n0) * CROW, B_ST, mb);
    };

    float acc[4][8][4];
#pragma unroll
    for (int a = 0; a < 4; a++)
#pragma unroll
        for (int b = 0; b < 8; b++)
#pragma unroll
            for (int q = 0; q < 4; q++) acc[a][b][q] = 0.f;

    if (tid == 0) { issue(0, 0); issue(1, 1); }
    int ph[2] = { 0, 0 };

    for (int c = 0; c < NCHUNK; c++) {
        int st = c & 1;
        mbar_wait(sb + st * 8, ph[st]); ph[st] ^= 1;
        uint32_t sbuf = stg + st * STG2;

#pragma unroll
        for (int kk = 0; kk < 4; kk++) {
            uint32_t ah[4][4], al[4][4], bh[4][4], bl[4][4];
            uint32_t abase = sbuf + (wm * 64 + (lane & 15)) * CROW + ((lane >> 4) & 1) * 16 + kk * 32;
#pragma unroll
            for (int mi = 0; mi < 4; mi++)
                LDSM4(ah[mi][0], ah[mi][1], ah[mi][2], ah[mi][3], abase + mi * 16 * CROW);
            // B: LDSM4 covers two n8 tiles (rows r..r+7 and r+8..r+15)
            uint32_t bbase = sbuf + 2 * A_ST +
                             (wn * 64 + (lane & 7) + ((lane >> 4) & 1) * 8) * CROW +
                             ((lane >> 3) & 1) * 16 + kk * 32;
#pragma unroll
            for (int nj = 0; nj < 4; nj++)
                LDSM4(bh[nj][0], bh[nj][1], bh[nj][2], bh[nj][3], bbase + nj * 16 * CROW);
#pragma unroll
            for (int nj = 0; nj < 4; nj++)
                LDSM4(bl[nj][0], bl[nj][1], bl[nj][2], bl[nj][3], bbase + B_ST + nj * 16 * CROW);
            // hi*hi and hi*lo first (ah live), then lo A
#pragma unroll
            for (int mi = 0; mi < 4; mi++)
#pragma unroll
                for (int nj = 0; nj < 4; nj++) {
                    MMA16816(acc[mi][2 * nj],     ah[mi], &bh[nj][0]);
                    MMA16816(acc[mi][2 * nj + 1], ah[mi], &bh[nj][2]);
                    MMA16816(acc[mi][2 * nj],     ah[mi], &bl[nj][0]);
                    MMA16816(acc[mi][2 * nj + 1], ah[mi], &bl[nj][2]);
                }
#pragma unroll
            for (int mi = 0; mi < 4; mi++)
                LDSM4(al[mi][0], al[mi][1], al[mi][2], al[mi][3], abase + A_ST + mi * 16 * CROW);
#pragma unroll
            for (int mi = 0; mi < 4; mi++)
#pragma unroll
                for (int nj = 0; nj < 4; nj++) {
                    MMA16816(acc[mi][2 * nj],     al[mi], &bh[nj][0]);
                    MMA16816(acc[mi][2 * nj + 1], al[mi], &bh[nj][2]);
                }
        }
        __syncthreads();
        if (tid == 0 && c + 2 < NCHUNK) issue(c + 2, st);
    }
    __syncthreads();

    // ---- stage C through smem (256 x 132) for coalesced writeout ----
    float* Cst = (float*)smem;
#pragma unroll
    for (int mi = 0; mi < 4; mi++)
#pragma unroll
        for (int nj = 0; nj < 4; nj++)
#pragma unroll
            for (int q = 0; q < 2; q++) {
                int ni = 2 * nj + q;
                int r = wm * 64 + mi * 16 + (lane >> 2);
                int cb = wn * 64 + nj * 16 + q * 8 + (lane & 3) * 2;
                Cst[r * 132 + cb]           = acc[mi][ni][0];
                Cst[r * 132 + cb + 1]       = acc[mi][ni][1];
                Cst[(r + 8) * 132 + cb]     = acc[mi][ni][2];
                Cst[(r + 8) * 132 + cb + 1] = acc[mi][ni][3];
            }
    __syncthreads();

    for (int it = tid; it < 256 * 32; it += 256) {
        int row = it >> 5;
        int col = (it & 31) * 4;
        int m = m0 + row;
        if (mode == 1 && m >= Mact) continue;
        float4 v = *(float4*)&Cst[row * 132 + col];
        float4 b1 = *(const float4*)(bias1 + n0 + col);
        v.x += b1.x; v.y += b1.y; v.z += b1.z; v.w += b1.w;
        float* dst;
        if (mode == 0) dst = outp + (size_t)m * NG + n0 + col;
        else           dst = outp + rowout[m] + n0 + col;
        *(float4*)dst = v;
    }
}

// ---------------- step 0 ----------------
__global__ void __launch_bounds__(256) k_step0()
{
    int b = blockIdx.x;
    for (int d = threadIdx.x; d < DDIM; d += 256) {
        float4 gx = *(const float4*)&d_gatesx[(size_t)b * NG + d * 4];
        float c = sigmf(gx.x) * tanhf(gx.z);
        float h = sigmf(gx.w) * tanhf(c);
        d_c[b * DDIM + d] = c;
        __nv_bfloat16 hh = __float2bfloat16(h);
        __nv_bfloat16 hl = __float2bfloat16(h - __bfloat162float(hh));
        int ch = d >> 6, kc = d & 63;
        size_t o = ((size_t)ch * BATCH + b) * CROW + kc * 2;
        *(__nv_bfloat16*)(d_HpHi[0] + o) = hh;
        *(__nv_bfloat16*)(d_HpLo[0] + o) = hl;
    }
}

// ---------------- fused recurrent step: 4-stage full prefetch ----------------
#define SOPA 9216
#define SOPB 18432
#define SSTG (2 * SOPA + 2 * SOPB)    // 55296 per chunk stage
#define SMEM_S (128 + 4 * SSTG)       // 221312: all 4 chunks resident

__global__ void __launch_bounds__(256, 1) k_stepf(int s)
{
    extern __shared__ char smem[];
    int tid = threadIdx.x;
    int nt = blockIdx.x, ks = blockIdx.y;
    int n0 = nt * 128;
    int rp = (s - 1) & 1, wp = s & 1;

    uint32_t sb  = smem_u32(smem);
    uint32_t stg = sb + 128;
    int wid = tid >> 5, lane = tid & 31;
    int wm = wid & 1, wn = wid >> 1;

    if (tid == 0) {
        MBAR_INIT(sb + 0, 1); MBAR_INIT(sb + 8, 1);
        MBAR_INIT(sb + 16, 1); MBAR_INIT(sb + 24, 1);
    }
    FENCE_ASYNC();
    __syncthreads();

    // issue ALL 4 chunk loads up-front (H from prev step is complete; Whh static)
    if (tid == 0) {
#pragma unroll
        for (int cc = 0; cc < 4; cc++) {
            uint32_t mb = sb + cc * 8;
            int cg = ks * 4 + cc;
            MBAR_EXPECT(mb, SSTG);
            uint32_t base = stg + cc * SSTG;
            BULKCP(base,                   d_HpHi[rp] + (size_t)cg * SOPA, SOPA, mb);
            BULKCP(base + SOPA,            d_HpLo[rp] + (size_t)cg * SOPA, SOPA, mb);
            BULKCP(base + 2 * SOPA,        d_WhhHiC + ((size_t)cg * NG + n0) * CROW, SOPB, mb);
            BULKCP(base + 2 * SOPA + SOPB, d_WhhLoC + ((size_t)cg * NG + n0) * CROW, SOPB, mb);
        }
    }

    float acc[2][4][4];
#pragma unroll
    for (int a = 0; a < 2; a++)
#pragma unroll
        for (int b = 0; b < 4; b++)
#pragma unroll
            for (int q = 0; q < 4; q++) acc[a][b][q] = 0.f;

    for (int c = 0; c < 4; c++) {
        mbar_wait(sb + c * 8, 0);        // each barrier completes exactly once
        uint32_t sbuf = stg + c * SSTG;
#pragma unroll
        for (int kk = 0; kk < 4; kk++) {
            uint32_t ah[2][4], al[2][4], bh[4][2], bl[4][2];
            uint32_t abase = sbuf + (wm * 32 + (lane & 15)) * CROW + (lane >> 4) * 16 + kk * 32;
#pragma unroll
            for (int mi = 0; mi < 2; mi++)
                LDSM4(ah[mi][0], ah[mi][1], ah[mi][2], ah[mi][3], abase + mi * 16 * CROW);
#pragma unroll
            for (int mi = 0; mi < 2; mi++)
                LDSM4(al[mi][0], al[mi][1], al[mi][2], al[mi][3], abase + SOPA + mi * 16 * CROW);
            uint32_t bbase = sbuf + 2 * SOPA + (wn * 32 + (lane & 7)) * CROW + ((lane >> 3) & 1) * 16 + kk * 32;
#pragma unroll
            for (int ni = 0; ni < 4; ni++)
                LDSM2(bh[ni][0], bh[ni][1], bbase + ni * 8 * CROW);
#pragma unroll
            for (int ni = 0; ni < 4; ni++)
                LDSM2(bl[ni][0], bl[ni][1], bbase + SOPB + ni * 8 * CROW);
#pragma unroll
            for (int mi = 0; mi < 2; mi++)
#pragma unroll
                for (int ni = 0; ni < 4; ni++) {
                    MMA16816(acc[mi][ni], ah[mi], bh[ni]);
                    MMA16816(acc[mi][ni], al[mi], bh[ni]);
                    MMA16816(acc[mi][ni], ah[mi], bl[ni]);
                }
        }
    }

#pragma unroll
    for (int mi = 0; mi < 2; mi++)
#pragma unroll
        for (int ni = 0; ni < 4; ni++) {
            int r = wm * 32 + mi * 16 + (lane >> 2);
            int col = n0 + wn * 32 + ni * 8 + (lane & 3) * 2;
            *(float2*)&d_part[ks][r][col]     = make_float2(acc[mi][ni][0], acc[mi][ni][1]);
            *(float2*)&d_part[ks][r + 8][col] = make_float2(acc[mi][ni][2], acc[mi][ni][3]);
        }
    __threadfence();
    __syncthreads();

    __shared__ int s_old;
    if (tid == 0) s_old = atomicAdd(&d_ncnt[nt], 1);
    __syncthreads();
    if (s_old != KSPLIT - 1) return;
    __threadfence();

    int cnt = d_cnt[s - 1];
    int rs  = d_rowstart[s - 1];
    int nd0 = n0 >> 2;
    for (int it = tid; it < BATCH * 32; it += 256) {
        int b = it >> 5, di = it & 31;
        int dim = nd0 + di;
        int ch = dim >> 6, kc = dim & 63;
        size_t hoff = ((size_t)ch * BATCH + b) * CROW + kc * 2;
        if (b < cnt) {
            float4 g = *(const float4*)&d_gatesx[((size_t)s * BATCH + b) * NG + dim * 4];
            float4 p0 = *(const float4*)&d_part[0][b][dim * 4];
            float4 p1 = *(const float4*)&d_part[1][b][dim * 4];
            float4 p2 = *(const float4*)&d_part[2][b][dim * 4];
            float4 p3 = *(const float4*)&d_part[3][b][dim * 4];
            float gi = g.x + p0.x + p1.x + p2.x + p3.x;
            float gf = g.y + p0.y + p1.y + p2.y + p3.y;
            float gg = g.z + p0.z + p1.z + p2.z + p3.z;
            float go = g.w + p0.w + p1.w + p2.w + p3.w;
            float cold = d_c[b * DDIM + dim];
            float cn = sigmf(gf) * cold + sigmf(gi) * tanhf(gg);
            float hn = sigmf(go) * tanhf(cn);
            d_c[b * DDIM + dim] = cn;
            __nv_bfloat16 hh = __float2bfloat16(hn);
            __nv_bfloat16 hl = __float2bfloat16(hn - __bfloat162float(hh));
            *(__nv_bfloat16*)(d_HpHi[wp] + hoff) = hh;
            *(__nv_bfloat16*)(d_HpLo[wp] + hoff) = hl;
            size_t co = ((size_t)ch * MROWS + rs + b) * CROW + kc * 2;
            *(__nv_bfloat16*)(d_HchiC + co) = hh;
            *(__nv_bfloat16*)(d_HcloC + co) = hl;
        } else {
            *(__nv_bfloat16*)(d_HpHi[wp] + hoff) = *(const __nv_bfloat16*)(d_HpHi[rp] + hoff);
            *(__nv_bfloat16*)(d_HpLo[wp] + hoff) = *(const __nv_bfloat16*)(d_HpLo[rp] + hoff);
        }
    }
    if (tid == 0) d_ncnt[nt] = 0;
}

// ---------------- launch ----------------
extern "C" void kernel_launch(void* const* d_in, const int* in_sizes, int n_in,
                              void* d_out, int out_size)
{
    const float* enc  = (const float*)d_in[0];
    const void*  caps = d_in[1];
    const void*  clen = d_in[2];
    const float* emb  = (const float*)d_in[3];
    const float* Wih  = (const float*)d_in[4];
    const float* Whh  = (const float*)d_in[5];
    const float* bih  = (const float*)d_in[6];
    const float* bhh  = (const float*)d_in[7];
    const float* fcW  = (const float*)d_in[8];
    const float* fcb  = (const float*)d_in[9];
    float* out = (float*)d_out;

    static cudaStream_t s2 = nullptr;
    static cudaEvent_t ev0 = nullptr, ev1 = nullptr, evW = nullptr;
    if (!s2) {
        cudaFuncSetAttribute(k_mma,   cudaFuncAttributeMaxDynamicSharedMemorySize, SMEMB);
        cudaFuncSetAttribute(k_stepf, cudaFuncAttributeMaxDynamicSharedMemorySize, SMEM_S);
        cudaStreamCreateWithFlags(&s2, cudaStreamNonBlocking);
        cudaEventCreateWithFlags(&ev0, cudaEventDisableTiming);
        cudaEventCreateWithFlags(&ev1, cudaEventDisableTiming);
        cudaEventCreateWithFlags(&evW, cudaEventDisableTiming);
    }

    char *pXhiC, *pXloC, *pHchiC, *pHcloC, *pWihHiC, *pWihLoC, *pWhhHiC, *pWhhLoC, *pWfcHiC, *pWfcLoC;
    float *pGatesx, *pBiasPk;
    long long* pRowout;
    int *pMact, *pM2048;
    cudaGetSymbolAddress((void**)&pXhiC, d_XhiC);
    cudaGetSymbolAddress((void**)&pXloC, d_XloC);
    cudaGetSymbolAddress((void**)&pHchiC, d_HchiC);
    cudaGetSymbolAddress((void**)&pHcloC, d_HcloC);
    cudaGetSymbolAddress((void**)&pWihHiC, d_WihHiC);
    cudaGetSymbolAddress((void**)&pWihLoC, d_WihLoC);
    cudaGetSymbolAddress((void**)&pWhhHiC, d_WhhHiC);
    cudaGetSymbolAddress((void**)&pWhhLoC, d_WhhLoC);
    cudaGetSymbolAddress((void**)&pWfcHiC, d_WfcHiC);
    cudaGetSymbolAddress((void**)&pWfcLoC, d_WfcLoC);
    cudaGetSymbolAddress((void**)&pGatesx, d_gatesx);
    cudaGetSymbolAddress((void**)&pBiasPk, d_biasPk);
    cudaGetSymbolAddress((void**)&pRowout, d_rowout);
    cudaGetSymbolAddress((void**)&pMact, d_Mact);
    cudaGetSymbolAddress((void**)&pM2048, d_M2048);

    // side stream: Whh split first (needed by step chain), then fc split + out memset
    cudaEventRecord(ev0, 0);
    cudaStreamWaitEvent(s2, ev0, 0);
    k_split<<<NG, 256, 0, s2>>>((const float4*)Whh, pWhhHiC, pWhhLoC, NG, 1);
    cudaEventRecord(evW, s2);
    k_split<<<VOCAB, 256, 0, s2>>>((const float4*)fcW, pWfcHiC, pWfcLoC, VOCAB, 0);
    cudaMemsetAsync(out, 0, (size_t)out_size * sizeof(float), s2);
    cudaEventRecord(ev1, s2);

    // main stream
    cudaMemsetAsync(pHchiC, 0, (size_t)NCHUNK * MROWS * CROW);
    cudaMemsetAsync(pHcloC, 0, (size_t)NCHUNK * MROWS * CROW);
    k_setup<<<1, 64>>>(clen);
    k_gather<<<TCAP * BATCH, 256>>>(enc, caps, emb);
    k_split<<<NG, 256>>>((const float4*)Wih, pWihHiC, pWihLoC, NG, 1);
    k_packbias<<<NG / 256, 256>>>(bih, bhh);

    // gates_x = X @ WihPk^T + biasPk   (M=2048, N=4096 packed)
    k_mma<<<dim3(8, 32), 256, SMEMB>>>(pXhiC, pXloC, pWihHiC, pWihLoC,
                                       MROWS, NG, pBiasPk, pGatesx,
                                       nullptr, pM2048, 0);

    k_step0<<<BATCH, 256>>>();
    cudaStreamWaitEvent(0, evW, 0);        // Whh split ready
    for (int s = 1; s <= TDEC; s++)
        k_stepf<<<dim3(NTILES, KSPLIT), 256, SMEM_S>>>(s);

    cudaStreamWaitEvent(0, ev1, 0);
    k_tail<<<1, 64>>>(out, out_size);

    // predictions = Hc @ fcW^T + fcb, scattered  (M=Mact compacted, N=32000)
    k_mma<<<dim3(8, 250), 256, SMEMB>>>(pHchiC, pHcloC, pWfcHiC, pWfcLoC,
                                        MROWS, VOCAB, fcb, out,
                                        pRowout, pMact, 1);
}

// round 17
// speedup vs baseline: 1.3559x; 1.3559x over previous
#include <cuda_runtime.h>
#include <cuda_bf16.h>
#include <cuda_fp16.h>
#include <cstdint>

#define BATCH 64
#define TCAP  32
#define VOCAB 32000
#define EDIM  1024
#define DDIM  1024
#define TDEC  31
#define NG    4096
#define MROWS 2048
#define CROW  144
#define NCHUNK 16
#define KSPLIT 4
#define NTILES 32          // 4096 / 128

// ---------------- static scratch ----------------
__device__ int   d_sortind[BATCH];
__device__ int   d_declen[BATCH];
__device__ int   d_cnt[TDEC];
__device__ int   d_rowstart[TDEC];
__device__ int   d_Mact;
__device__ int   d_M2048 = 2048;
__device__ int   d_i64;
__device__ int   d_ncnt[NTILES];
__device__ long long d_rowout[MROWS];
__device__ __align__(16) float d_gatesx[TCAP * BATCH * NG];   // gate-PACKED cols
__device__ __align__(16) float d_biasPk[NG];
__device__ __align__(16) float d_c[BATCH * DDIM];
__device__ __align__(16) float d_part[KSPLIT][BATCH][NG];
// chunked + padded operands: [chunk][row][144B]
__device__ __align__(16) char d_XhiC [NCHUNK * MROWS * CROW];
__device__ __align__(16) char d_XloC [NCHUNK * MROWS * CROW];
__device__ __align__(16) char d_HfC  [NCHUNK * MROWS * CROW];   // fp16 h for fc
__device__ __align__(16) char d_WihHiC[NCHUNK * NG * CROW];     // gate-packed rows
__device__ __align__(16) char d_WihLoC[NCHUNK * NG * CROW];
__device__ __align__(16) char d_WhhHiC[NCHUNK * NG * CROW];
__device__ __align__(16) char d_WhhLoC[NCHUNK * NG * CROW];
__device__ __align__(16) char d_WfcF [NCHUNK * VOCAB * CROW];   // fp16 fc_W
__device__ __align__(16) char d_HpHi[2][NCHUNK * BATCH * CROW];
__device__ __align__(16) char d_HpLo[2][NCHUNK * BATCH * CROW];

__device__ __forceinline__ float sigmf(float x) { return 1.0f / (1.0f + expf(-x)); }

__device__ __forceinline__ uint32_t smem_u32(const void* p) {
    uint32_t a;
    asm("{ .reg .u64 t; cvta.to.shared.u64 t, %1; cvt.u32.u64 %0, t; }" : "=r"(a) : "l"(p));
    return a;
}

#define LDSM4(r0, r1, r2, r3, a) \
    asm volatile("ldmatrix.sync.aligned.m8n8.x4.shared.b16 {%0,%1,%2,%3}, [%4];" \
                 : "=r"(r0), "=r"(r1), "=r"(r2), "=r"(r3) : "r"(a))
#define LDSM2(r0, r1, a) \
    asm volatile("ldmatrix.sync.aligned.m8n8.x2.shared.b16 {%0,%1}, [%2];" \
                 : "=r"(r0), "=r"(r1) : "r"(a))
#define MMA16816(c, a, b) \
    asm volatile("mma.sync.aligned.m16n8k16.row.col.f32.bf16.bf16.f32 " \
                 "{%0,%1,%2,%3}, {%4,%5,%6,%7}, {%8,%9}, {%0,%1,%2,%3};" \
                 : "+f"((c)[0]), "+f"((c)[1]), "+f"((c)[2]), "+f"((c)[3]) \
                 : "r"((a)[0]), "r"((a)[1]), "r"((a)[2]), "r"((a)[3]), "r"((b)[0]), "r"((b)[1]))
#define MMAF16(c, a, b) \
    asm volatile("mma.sync.aligned.m16n8k16.row.col.f32.f16.f16.f32 " \
                 "{%0,%1,%2,%3}, {%4,%5,%6,%7}, {%8,%9}, {%0,%1,%2,%3};" \
                 : "+f"((c)[0]), "+f"((c)[1]), "+f"((c)[2]), "+f"((c)[3]) \
                 : "r"((a)[0]), "r"((a)[1]), "r"((a)[2]), "r"((a)[3]), "r"((b)[0]), "r"((b)[1]))
#define MBAR_INIT(a, c)  asm volatile("mbarrier.init.shared.b64 [%0], %1;" :: "r"(a), "r"(c) : "memory")
#define MBAR_EXPECT(a, tx) asm volatile("mbarrier.arrive.expect_tx.shared.b64 _, [%0], %1;" :: "r"(a), "r"(tx) : "memory")
#define FENCE_ASYNC()    asm volatile("fence.proxy.async.shared::cta;" ::: "memory")
#define BULKCP(dst, src, sz, mb) \
    asm volatile("cp.async.bulk.shared::cluster.global.mbarrier::complete_tx::bytes [%0], [%1], %2, [%3];" \
                 :: "r"(dst), "l"(src), "r"(sz), "r"(mb) : "memory")

__device__ __forceinline__ void mbar_wait(uint32_t mb, uint32_t parity) {
    asm volatile(
        "{\n\t.reg .pred P;\n\t"
        "W%=:\n\t"
        "mbarrier.try_wait.parity.acquire.cta.shared::cta.b64 P, [%0], %1, 0x989680;\n\t"
        "@P bra.uni D%=;\n\t"
        "bra.uni W%=;\n\t"
        "D%=:\n\t}" :: "r"(mb), "r"(parity) : "memory");
}

// ---------------- setup ----------------
__global__ void k_setup(const void* __restrict__ cap_len_raw)
{
    __shared__ int len[BATCH];
    const int* p32 = (const int*)cap_len_raw;
    int is64 = (p32[1] == 0) ? 1 : 0;   // lengths in [2,32]; int64 high word == 0
    int i = threadIdx.x;
    if (i == 0) d_i64 = is64;
    if (i < BATCH) len[i] = p32[i << is64];
    __syncthreads();
    if (i < BATCH) {
        int li = len[i], r = 0;
        for (int j = 0; j < BATCH; j++) {
            int lj = len[j];
            if (lj > li || (lj == li && j < i)) r++;
        }
        d_sortind[r] = i;
        d_declen[r]  = li - 1;
    }
    __syncthreads();
    if (i < TDEC) {
        int c = 0;
        for (int b = 0; b < BATCH; b++)
            if (d_declen[b] > i) c++;
        d_cnt[i] = c;
    }
    __syncthreads();
    if (i == 0) {
        int acc = 0;
        for (int s = 0; s < TDEC; s++) { d_rowstart[s] = acc; acc += d_cnt[s]; }
        d_Mact = acc;
    }
    __syncthreads();
    for (int s = 0; s < TDEC; s++)
        if (i < d_cnt[s])
            d_rowout[d_rowstart[s] + i] = ((long long)i * TDEC + s) * VOCAB;
}

__global__ void k_tail(float* __restrict__ out, int out_size)
{
    int i = threadIdx.x;
    long long base = (long long)BATCH * TDEC * VOCAB;
    if (out_size >= (int)(base + 2 * BATCH) && i < BATCH) {
        out[base + i]         = (float)d_declen[i];
        out[base + BATCH + i] = (float)d_sortind[i];
    }
}

__global__ void k_packbias(const float* __restrict__ bih, const float* __restrict__ bhh)
{
    int p = blockIdx.x * 256 + threadIdx.x;
    int o = (p & 3) * 1024 + (p >> 2);
    d_biasPk[p] = bih[o] + bhh[o];
}

// ---------------- gather ----------------
__global__ void __launch_bounds__(256) k_gather(const float* __restrict__ enc,
                                                const void* __restrict__ caps_raw,
                                                const float* __restrict__ emb)
{
    int row = blockIdx.x;
    int t = row >> 6, b = row & 63;
    int sb = d_sortind[b];
    const float* src;
    if (t == 0) {
        src = enc + (long long)sb * EDIM;
    } else {
        int idx = sb * TCAP + (t - 1);
        int tok = ((const int*)caps_raw)[idx << d_i64];
        src = emb + (long long)tok * EDIM;
    }
    float4 v = ((const float4*)src)[threadIdx.x];
    __nv_bfloat16 hx = __float2bfloat16(v.x), hy = __float2bfloat16(v.y);
    __nv_bfloat16 hz = __float2bfloat16(v.z), hw = __float2bfloat16(v.w);
    __nv_bfloat162 hA; hA.x = hx; hA.y = hy;
    __nv_bfloat162 hB; hB.x = hz; hB.y = hw;
    __nv_bfloat162 lA, lB;
    lA.x = __float2bfloat16(v.x - __bfloat162float(hx));
    lA.y = __float2bfloat16(v.y - __bfloat162float(hy));
    lB.x = __float2bfloat16(v.z - __bfloat162float(hz));
    lB.y = __float2bfloat16(v.w - __bfloat162float(hw));
    int col = threadIdx.x * 4;
    int ch = col >> 6, kc = col & 63;
    size_t off = ((size_t)ch * MROWS + row) * CROW + kc * 2;
    *(__nv_bfloat162*)(d_XhiC + off)     = hA;
    *(__nv_bfloat162*)(d_XhiC + off + 4) = hB;
    *(__nv_bfloat162*)(d_XloC + off)     = lA;
    *(__nv_bfloat162*)(d_XloC + off + 4) = lB;
}

// ---------------- split weights (bf16 hi/lo) ----------------
__global__ void __launch_bounds__(256) k_split(const float4* __restrict__ src,
                                               char* __restrict__ hiC,
                                               char* __restrict__ loC, int nrows, int perm)
{
    int r = blockIdx.x;
    int p = perm ? ((r & 1023) * 4 + (r >> 10)) : r;
    int tid = threadIdx.x;
    float4 v = src[(size_t)r * 256 + tid];
    __nv_bfloat16 hx = __float2bfloat16(v.x), hy = __float2bfloat16(v.y);
    __nv_bfloat16 hz = __float2bfloat16(v.z), hw = __float2bfloat16(v.w);
    __nv_bfloat162 hA; hA.x = hx; hA.y = hy;
    __nv_bfloat162 hB; hB.x = hz; hB.y = hw;
    __nv_bfloat162 lA, lB;
    lA.x = __float2bfloat16(v.x - __bfloat162float(hx));
    lA.y = __float2bfloat16(v.y - __bfloat162float(hy));
    lB.x = __float2bfloat16(v.z - __bfloat162float(hz));
    lB.y = __float2bfloat16(v.w - __bfloat162float(hw));
    int col = tid * 4;
    int ch = col >> 6, kc = col & 63;
    size_t off = ((size_t)ch * nrows + p) * CROW + kc * 2;
    *(__nv_bfloat162*)(hiC + off)     = hA;
    *(__nv_bfloat162*)(hiC + off + 4) = hB;
    *(__nv_bfloat162*)(loC + off)     = lA;
    *(__nv_bfloat162*)(loC + off + 4) = lB;
}

// ---------------- fc weight -> fp16 chunked ----------------
__global__ void __launch_bounds__(256) k_halfW(const float4* __restrict__ src,
                                               char* __restrict__ outC)
{
    int r = blockIdx.x;
    int tid = threadIdx.x;
    float4 v = src[(size_t)r * 256 + tid];
    __half2 a; a.x = __float2half(v.x); a.y = __float2half(v.y);
    __half2 b; b.x = __float2half(v.z); b.y = __float2half(v.w);
    int col = tid * 4;
    int ch = col >> 6, kc = col & 63;
    size_t off = ((size_t)ch * VOCAB + r) * CROW + kc * 2;
    *(__half2*)(outC + off)     = a;
    *(__half2*)(outC + off + 4) = b;
}

// ================= bf16 3-term bulk-copy GEMM (256x128) — round-12 proven =================
#define A_ST   (256 * CROW)          // 36864
#define B_ST   (128 * CROW)          // 18432
#define STG2   (2 * A_ST + 2 * B_ST) // 110592 per stage
#define SMEMB  (128 + 2 * STG2)      // 221312

__global__ void __launch_bounds__(256, 1) k_mma(
    const char* __restrict__ AhiC, const char* __restrict__ AloC,
    const char* __restrict__ BhiC, const char* __restrict__ BloC,
    int arows, int brows,
    const float* __restrict__ bias1,
    float* __restrict__ outp, const long long* __restrict__ rowout,
    const int* __restrict__ pMact, int mode)
{
    extern __shared__ char smem[];
    int tid = threadIdx.x;
    int m0 = blockIdx.x * 256;
    int n0 = blockIdx.y * 128;
    int Mact = *pMact;
    if (m0 >= Mact) return;

    uint32_t sb  = smem_u32(smem);
    uint32_t stg = sb + 128;
    int wid = tid >> 5, lane = tid & 31;
    int wm = wid >> 1, wn = wid & 1;      // warp tile 64x64

    if (tid == 0) { MBAR_INIT(sb + 0, 1); MBAR_INIT(sb + 8, 1); }
    FENCE_ASYNC();
    __syncthreads();

    auto issue = [&](int c, int slot) {
        uint32_t mb = sb + slot * 8;
        MBAR_EXPECT(mb, STG2);
        uint32_t base = stg + slot * STG2;
        BULKCP(base,                AhiC + ((size_t)c * arows + m0) * CROW, A_ST, mb);
        BULKCP(base + A_ST,         AloC + ((size_t)c * arows + m0) * CROW, A_ST, mb);
        BULKCP(base + 2 * A_ST,         BhiC + ((size_t)c * brows + n0) * CROW, B_ST, mb);
        BULKCP(base + 2 * A_ST + B_ST,  BloC + ((size_t)c * brows + n0) * CROW, B_ST, mb);
    };

    float acc[4][8][4];
#pragma unroll
    for (int a = 0; a < 4; a++)
#pragma unroll
        for (int b = 0; b < 8; b++)
#pragma unroll
            for (int q = 0; q < 4; q++) acc[a][b][q] = 0.f;

    if (tid == 0) { issue(0, 0); issue(1, 1); }
    int ph[2] = { 0, 0 };

    for (int c = 0; c < NCHUNK; c++) {
        int st = c & 1;
        mbar_wait(sb + st * 8, ph[st]); ph[st] ^= 1;
        uint32_t sbuf = stg + st * STG2;

#pragma unroll
        for (int kk = 0; kk < 4; kk++) {
            uint32_t ah[4][4], al[4][4], bh[4][4], bl[4][4];
            uint32_t abase = sbuf + (wm * 64 + (lane & 15)) * CROW + ((lane >> 4) & 1) * 16 + kk * 32;
#pragma unroll
            for (int mi = 0; mi < 4; mi++)
                LDSM4(ah[mi][0], ah[mi][1], ah[mi][2], ah[mi][3], abase + mi * 16 * CROW);
            uint32_t bbase = sbuf + 2 * A_ST +
                             (wn * 64 + (lane & 7) + ((lane >> 4) & 1) * 8) * CROW +
                             ((lane >> 3) & 1) * 16 + kk * 32;
#pragma unroll
            for (int nj = 0; nj < 4; nj++)
                LDSM4(bh[nj][0], bh[nj][1], bh[nj][2], bh[nj][3], bbase + nj * 16 * CROW);
#pragma unroll
            for (int nj = 0; nj < 4; nj++)
                LDSM4(bl[nj][0], bl[nj][1], bl[nj][2], bl[nj][3], bbase + B_ST + nj * 16 * CROW);
#pragma unroll
            for (int mi = 0; mi < 4; mi++)
#pragma unroll
                for (int nj = 0; nj < 4; nj++) {
                    MMA16816(acc[mi][2 * nj],     ah[mi], &bh[nj][0]);
                    MMA16816(acc[mi][2 * nj + 1], ah[mi], &bh[nj][2]);
                    MMA16816(acc[mi][2 * nj],     ah[mi], &bl[nj][0]);
                    MMA16816(acc[mi][2 * nj + 1], ah[mi], &bl[nj][2]);
                }
#pragma unroll
            for (int mi = 0; mi < 4; mi++)
                LDSM4(al[mi][0], al[mi][1], al[mi][2], al[mi][3], abase + A_ST + mi * 16 * CROW);
#pragma unroll
            for (int mi = 0; mi < 4; mi++)
#pragma unroll
                for (int nj = 0; nj < 4; nj++) {
                    MMA16816(acc[mi][2 * nj],     al[mi], &bh[nj][0]);
                    MMA16816(acc[mi][2 * nj + 1], al[mi], &bh[nj][2]);
                }
        }
        __syncthreads();
        if (tid == 0 && c + 2 < NCHUNK) issue(c + 2, st);
    }
    __syncthreads();

    float* Cst = (float*)smem;           // 256 x 132
#pragma unroll
    for (int mi = 0; mi < 4; mi++)
#pragma unroll
        for (int nj = 0; nj < 4; nj++)
#pragma unroll
            for (int q = 0; q < 2; q++) {
                int ni = 2 * nj + q;
                int r = wm * 64 + mi * 16 + (lane >> 2);
                int cb = wn * 64 + nj * 16 + q * 8 + (lane & 3) * 2;
                Cst[r * 132 + cb]           = acc[mi][ni][0];
                Cst[r * 132 + cb + 1]       = acc[mi][ni][1];
                Cst[(r + 8) * 132 + cb]     = acc[mi][ni][2];
                Cst[(r + 8) * 132 + cb + 1] = acc[mi][ni][3];
            }
    __syncthreads();

    for (int it = tid; it < 256 * 32; it += 256) {
        int row = it >> 5;
        int col = (it & 31) * 4;
        int m = m0 + row;
        if (mode == 1 && m >= Mact) continue;
        float4 v = *(float4*)&Cst[row * 132 + col];
        float4 b1 = *(const float4*)(bias1 + n0 + col);
        v.x += b1.x; v.y += b1.y; v.z += b1.z; v.w += b1.w;
        float* dst;
        if (mode == 0) dst = outp + (size_t)m * NG + n0 + col;
        else           dst = outp + rowout[m] + n0 + col;
        *(float4*)dst = v;
    }
}

// ================= fp16 1-term fc GEMM — exact clone of k_mma minus lo operands =================
#define STGF   (A_ST + B_ST)         // 55296 per stage
#define SMEMF  (128 + 256 * 132 * 4) // 135296 (C staging dominates; stages use 110720)

__global__ void __launch_bounds__(256, 1) k_mma_f16(
    const char* __restrict__ AC, const char* __restrict__ BC,
    const float* __restrict__ bias1,
    float* __restrict__ outp, const long long* __restrict__ rowout,
    const int* __restrict__ pMact)
{
    extern __shared__ char smem[];
    int tid = threadIdx.x;
    int m0 = blockIdx.x * 256;
    int n0 = blockIdx.y * 128;
    int Mact = *pMact;
    if (m0 >= Mact) return;

    uint32_t sb  = smem_u32(smem);
    uint32_t stg = sb + 128;
    int wid = tid >> 5, lane = tid & 31;
    int wm = wid >> 1, wn = wid & 1;      // warp tile 64x64 (identical to k_mma)

    if (tid == 0) { MBAR_INIT(sb + 0, 1); MBAR_INIT(sb + 8, 1); }
    FENCE_ASYNC();
    __syncthreads();

    auto issue = [&](int c, int slot) {
        uint32_t mb = sb + slot * 8;
        MBAR_EXPECT(mb, STGF);
        uint32_t base = stg + slot * STGF;
        BULKCP(base,        AC + ((size_t)c * MROWS + m0) * CROW, A_ST, mb);
        BULKCP(base + A_ST, BC + ((size_t)c * VOCAB + n0) * CROW, B_ST, mb);
    };

    float acc[4][8][4];
#pragma unroll
    for (int a = 0; a < 4; a++)
#pragma unroll
        for (int b = 0; b < 8; b++)
#pragma unroll
            for (int q = 0; q < 4; q++) acc[a][b][q] = 0.f;

    if (tid == 0) { issue(0, 0); issue(1, 1); }
    int ph[2] = { 0, 0 };

    for (int c = 0; c < NCHUNK; c++) {
        int st = c & 1;
        mbar_wait(sb + st * 8, ph[st]); ph[st] ^= 1;
        uint32_t sbuf = stg + st * STGF;

#pragma unroll
        for (int kk = 0; kk < 4; kk++) {
            uint32_t ah[4][4], bh[4][4];
            uint32_t abase = sbuf + (wm * 64 + (lane & 15)) * CROW + ((lane >> 4) & 1) * 16 + kk * 32;
#pragma unroll
            for (int mi = 0; mi < 4; mi++)
                LDSM4(ah[mi][0], ah[mi][1], ah[mi][2], ah[mi][3], abase + mi * 16 * CROW);
            uint32_t bbase = sbuf + A_ST +
                             (wn * 64 + (lane & 7) + ((lane >> 4) & 1) * 8) * CROW +
                             ((lane >> 3) & 1) * 16 + kk * 32;
#pragma unroll
            for (int nj = 0; nj < 4; nj++)
                LDSM4(bh[nj][0], bh[nj][1], bh[nj][2], bh[nj][3], bbase + nj * 16 * CROW);
#pragma unroll
            for (int mi = 0; mi < 4; mi++)
#pragma unroll
                for (int nj = 0; nj < 4; nj++) {
                    MMAF16(acc[mi][2 * nj],     ah[mi], &bh[nj][0]);
                    MMAF16(acc[mi][2 * nj + 1], ah[mi], &bh[nj][2]);
                }
        }
        __syncthreads();
        if (tid == 0 && c + 2 < NCHUNK) issue(c + 2, st);
    }
    __syncthreads();

    float* Cst = (float*)smem;           // 256 x 132 floats = 135168 <= SMEMF-128
#pragma unroll
    for (int mi = 0; mi < 4; mi++)
#pragma unroll
        for (int nj = 0; nj < 4; nj++)
#pragma unroll
            for (int q = 0; q < 2; q++) {
                int ni = 2 * nj + q;
                int r = wm * 64 + mi * 16 + (lane >> 2);
                int cb = wn * 64 + nj * 16 + q * 8 + (lane & 3) * 2;
                Cst[r * 132 + cb]           = acc[mi][ni][0];
                Cst[r * 132 + cb + 1]       = acc[mi][ni][1];
                Cst[(r + 8) * 132 + cb]     = acc[mi][ni][2];
                Cst[(r + 8) * 132 + cb + 1] = acc[mi][ni][3];
            }
    __syncthreads();

    for (int it = tid; it < 256 * 32; it += 256) {
        int row = it >> 5;
        int col = (it & 31) * 4;
        int m = m0 + row;
        if (m >= Mact) continue;
        float4 v = *(float4*)&Cst[row * 132 + col];
        float4 b1 = *(const float4*)(bias1 + n0 + col);
        v.x += b1.x; v.y += b1.y; v.z += b1.z; v.w += b1.w;
        *(float4*)(outp + rowout[m] + n0 + col) = v;
    }
}

// ---------------- step 0 ----------------
__global__ void __launch_bounds__(256) k_step0()
{
    int b = blockIdx.x;
    for (int d = threadIdx.x; d < DDIM; d += 256) {
        float4 gx = *(const float4*)&d_gatesx[(size_t)b * NG + d * 4];
        float c = sigmf(gx.x) * tanhf(gx.z);
        float h = sigmf(gx.w) * tanhf(c);
        d_c[b * DDIM + d] = c;
        __nv_bfloat16 hh = __float2bfloat16(h);
        __nv_bfloat16 hl = __float2bfloat16(h - __bfloat162float(hh));
        int ch = d >> 6, kc = d & 63;
        size_t o = ((size_t)ch * BATCH + b) * CROW + kc * 2;
        *(__nv_bfloat16*)(d_HpHi[0] + o) = hh;
        *(__nv_bfloat16*)(d_HpLo[0] + o) = hl;
    }
}

// ---------------- fused recurrent step (round-12 proven; epilogue writes fp16 h) ----------------
#define SOPA 9216
#define SOPB 18432
#define SSTG (2 * SOPA + 2 * SOPB)
#define SMEM_S (128 + 2 * SSTG)

__global__ void __launch_bounds__(256, 1) k_stepf(int s)
{
    extern __shared__ char smem[];
    int tid = threadIdx.x;
    int nt = blockIdx.x, ks = blockIdx.y;
    int n0 = nt * 128;
    int rp = (s - 1) & 1, wp = s & 1;

    uint32_t sb  = smem_u32(smem);
    uint32_t stg = sb + 128;
    int wid = tid >> 5, lane = tid & 31;
    int wm = wid & 1, wn = wid >> 1;

    if (tid == 0) { MBAR_INIT(sb + 0, 1); MBAR_INIT(sb + 8, 1); }
    FENCE_ASYNC();
    __syncthreads();

    auto issue = [&](int cc, int slot) {
        uint32_t mb = sb + slot * 8;
        int cg = ks * 4 + cc;
        MBAR_EXPECT(mb, SSTG);
        uint32_t base = stg + slot * SSTG;
        BULKCP(base,                   d_HpHi[rp] + (size_t)cg * SOPA, SOPA, mb);
        BULKCP(base + SOPA,            d_HpLo[rp] + (size_t)cg * SOPA, SOPA, mb);
        BULKCP(base + 2 * SOPA,        d_WhhHiC + ((size_t)cg * NG + n0) * CROW, SOPB, mb);
        BULKCP(base + 2 * SOPA + SOPB, d_WhhLoC + ((size_t)cg * NG + n0) * CROW, SOPB, mb);
    };

    float acc[2][4][4];
#pragma unroll
    for (int a = 0; a < 2; a++)
#pragma unroll
        for (int b = 0; b < 4; b++)
#pragma unroll
            for (int q = 0; q < 4; q++) acc[a][b][q] = 0.f;

    if (tid == 0) { issue(0, 0); issue(1, 1); }
    int ph[2] = { 0, 0 };

    for (int c = 0; c < 4; c++) {
        int st = c & 1;
        mbar_wait(sb + st * 8, ph[st]); ph[st] ^= 1;
        uint32_t sbuf = stg + st * SSTG;
#pragma unroll
        for (int kk = 0; kk < 4; kk++) {
            uint32_t ah[2][4], al[2][4], bh[4][2], bl[4][2];
            uint32_t abase = sbuf + (wm * 32 + (lane & 15)) * CROW + (lane >> 4) * 16 + kk * 32;
#pragma unroll
            for (int mi = 0; mi < 2; mi++)
                LDSM4(ah[mi][0], ah[mi][1], ah[mi][2], ah[mi][3], abase + mi * 16 * CROW);
#pragma unroll
            for (int mi = 0; mi < 2; mi++)
                LDSM4(al[mi][0], al[mi][1], al[mi][2], al[mi][3], abase + SOPA + mi * 16 * CROW);
            uint32_t bbase = sbuf + 2 * SOPA + (wn * 32 + (lane & 7)) * CROW + ((lane >> 3) & 1) * 16 + kk * 32;
#pragma unroll
            for (int ni = 0; ni < 4; ni++)
                LDSM2(bh[ni][0], bh[ni][1], bbase + ni * 8 * CROW);
#pragma unroll
            for (int ni = 0; ni < 4; ni++)
                LDSM2(bl[ni][0], bl[ni][1], bbase + SOPB + ni * 8 * CROW);
#pragma unroll
            for (int mi = 0; mi < 2; mi++)
#pragma unroll
                for (int ni = 0; ni < 4; ni++) {
                    MMA16816(acc[mi][ni], ah[mi], bh[ni]);
                    MMA16816(acc[mi][ni], al[mi], bh[ni]);
                    MMA16816(acc[mi][ni], ah[mi], bl[ni]);
                }
        }
        __syncthreads();
        if (tid == 0 && c + 2 < 4) issue(c + 2, st);
    }

#pragma unroll
    for (int mi = 0; mi < 2; mi++)
#pragma unroll
        for (int ni = 0; ni < 4; ni++) {
            int r = wm * 32 + mi * 16 + (lane >> 2);
            int col = n0 + wn * 32 + ni * 8 + (lane & 3) * 2;
            *(float2*)&d_part[ks][r][col]     = make_float2(acc[mi][ni][0], acc[mi][ni][1]);
            *(float2*)&d_part[ks][r + 8][col] = make_float2(acc[mi][ni][2], acc[mi][ni][3]);
        }
    __threadfence();
    __syncthreads();

    __shared__ int s_old;
    if (tid == 0) s_old = atomicAdd(&d_ncnt[nt], 1);
    __syncthreads();
    if (s_old != KSPLIT - 1) return;
    __threadfence();

    int cnt = d_cnt[s - 1];
    int rs  = d_rowstart[s - 1];
    int nd0 = n0 >> 2;
    for (int it = tid; it < BATCH * 32; it += 256) {
        int b = it >> 5, di = it & 31;
        int dim = nd0 + di;
        int ch = dim >> 6, kc = dim & 63;
        size_t hoff = ((size_t)ch * BATCH + b) * CROW + kc * 2;
        if (b < cnt) {
            float4 g = *(const float4*)&d_gatesx[((size_t)s * BATCH + b) * NG + dim * 4];
            float4 p0 = *(const float4*)&d_part[0][b][dim * 4];
            float4 p1 = *(const float4*)&d_part[1][b][dim * 4];
            float4 p2 = *(const float4*)&d_part[2][b][dim * 4];
            float4 p3 = *(const float4*)&d_part[3][b][dim * 4];
            float gi = g.x + p0.x + p1.x + p2.x + p3.x;
            float gf = g.y + p0.y + p1.y + p2.y + p3.y;
            float gg = g.z + p0.z + p1.z + p2.z + p3.z;
            float go = g.w + p0.w + p1.w + p2.w + p3.w;
            float cold = d_c[b * DDIM + dim];
            float cn = sigmf(gf) * cold + sigmf(gi) * tanhf(gg);
            float hn = sigmf(go) * tanhf(cn);
            d_c[b * DDIM + dim] = cn;
            __nv_bfloat16 hh = __float2bfloat16(hn);
            __nv_bfloat16 hl = __float2bfloat16(hn - __bfloat162float(hh));
            *(__nv_bfloat16*)(d_HpHi[wp] + hoff) = hh;
            *(__nv_bfloat16*)(d_HpLo[wp] + hoff) = hl;
            size_t co = ((size_t)ch * MROWS + rs + b) * CROW + kc * 2;
            *(__half*)(d_HfC + co) = __float2half(hn);
        } else {
            *(__nv_bfloat16*)(d_HpHi[wp] + hoff) = *(const __nv_bfloat16*)(d_HpHi[rp] + hoff);
            *(__nv_bfloat16*)(d_HpLo[wp] + hoff) = *(const __nv_bfloat16*)(d_HpLo[rp] + hoff);
        }
    }
    if (tid == 0) d_ncnt[nt] = 0;
}

// ---------------- launch ----------------
extern "C" void kernel_launch(void* const* d_in, const int* in_sizes, int n_in,
                              void* d_out, int out_size)
{
    const float* enc  = (const float*)d_in[0];
    const void*  caps = d_in[1];
    const void*  clen = d_in[2];
    const float* emb  = (const float*)d_in[3];
    const float* Wih  = (const float*)d_in[4];
    const float* Whh  = (const float*)d_in[5];
    const float* bih  = (const float*)d_in[6];
    const float* bhh  = (const float*)d_in[7];
    const float* fcW  = (const float*)d_in[8];
    const float* fcb  = (const float*)d_in[9];
    float* out = (float*)d_out;

    static cudaStream_t s2 = nullptr;
    static cudaEvent_t ev0 = nullptr, ev1 = nullptr, evW = nullptr;
    if (!s2) {
        cudaFuncSetAttribute(k_mma,     cudaFuncAttributeMaxDynamicSharedMemorySize, SMEMB);
        cudaFuncSetAttribute(k_mma_f16, cudaFuncAttributeMaxDynamicSharedMemorySize, SMEMF);
        cudaFuncSetAttribute(k_stepf,   cudaFuncAttributeMaxDynamicSharedMemorySize, SMEM_S);
        cudaStreamCreateWithFlags(&s2, cudaStreamNonBlocking);
        cudaEventCreateWithFlags(&ev0, cudaEventDisableTiming);
        cudaEventCreateWithFlags(&ev1, cudaEventDisableTiming);
        cudaEventCreateWithFlags(&evW, cudaEventDisableTiming);
    }

    char *pXhiC, *pXloC, *pHfC, *pWihHiC, *pWihLoC, *pWhhHiC, *pWhhLoC, *pWfcF;
    float *pGatesx, *pBiasPk;
    long long* pRowout;
    int *pMact, *pM2048;
    cudaGetSymbolAddress((void**)&pXhiC, d_XhiC);
    cudaGetSymbolAddress((void**)&pXloC, d_XloC);
    cudaGetSymbolAddress((void**)&pHfC, d_HfC);
    cudaGetSymbolAddress((void**)&pWihHiC, d_WihHiC);
    cudaGetSymbolAddress((void**)&pWihLoC, d_WihLoC);
    cudaGetSymbolAddress((void**)&pWhhHiC, d_WhhHiC);
    cudaGetSymbolAddress((void**)&pWhhLoC, d_WhhLoC);
    cudaGetSymbolAddress((void**)&pWfcF, d_WfcF);
    cudaGetSymbolAddress((void**)&pGatesx, d_gatesx);
    cudaGetSymbolAddress((void**)&pBiasPk, d_biasPk);
    cudaGetSymbolAddress((void**)&pRowout, d_rowout);
    cudaGetSymbolAddress((void**)&pMact, d_Mact);
    cudaGetSymbolAddress((void**)&pM2048, d_M2048);

    // side stream: Whh split (needed by steps), then fc fp16 weights + out memset
    cudaEventRecord(ev0, 0);
    cudaStreamWaitEvent(s2, ev0, 0);
    k_split<<<NG, 256, 0, s2>>>((const float4*)Whh, pWhhHiC, pWhhLoC, NG, 1);
    cudaEventRecord(evW, s2);
    k_halfW<<<VOCAB, 256, 0, s2>>>((const float4*)fcW, pWfcF);
    cudaMemsetAsync(out, 0, (size_t)out_size * sizeof(float), s2);
    cudaEventRecord(ev1, s2);

    // main stream
    cudaMemsetAsync(pHfC, 0, (size_t)NCHUNK * MROWS * CROW);
    k_setup<<<1, 64>>>(clen);
    k_gather<<<TCAP * BATCH, 256>>>(enc, caps, emb);
    k_split<<<NG, 256>>>((const float4*)Wih, pWihHiC, pWihLoC, NG, 1);
    k_packbias<<<NG / 256, 256>>>(bih, bhh);

    // gates_x = X @ WihPk^T + biasPk   (M=2048, N=4096 packed)
    k_mma<<<dim3(8, 32), 256, SMEMB>>>(pXhiC, pXloC, pWihHiC, pWihLoC,
                                       MROWS, NG, pBiasPk, pGatesx,
                                       nullptr, pM2048, 0);

    k_step0<<<BATCH, 256>>>();
    cudaStreamWaitEvent(0, evW, 0);
    for (int s = 1; s <= TDEC; s++)
        k_stepf<<<dim3(NTILES, KSPLIT), 256, SMEM_S>>>(s);

    cudaStreamWaitEvent(0, ev1, 0);
    k_tail<<<1, 64>>>(out, out_size);

    // predictions = Hf @ WfcF^T + fcb (fp16 1-term), scattered
    k_mma_f16<<<dim3(8, 250), 256, SMEMF>>>(pHfC, pWfcF, fcb, out, pRowout, pMact);
}